// round 7
// baseline (speedup 1.0000x reference)
#include <cuda_runtime.h>
#include <cuda_bf16.h>
#include <cstdint>

#define T_STEPS 512
#define BATCH   64
#define DIN     1024
#define HID     128
#define GATES   512   // 4*HID

// Scratch: x1[t][b][g] = feats @ W_ih1^T + b_ih1 + b_hh1   (64 MB)
__device__ float g_x1[(size_t)T_STEPS * BATCH * GATES];

// ---------------------------------------------------------------------------
// helpers
// ---------------------------------------------------------------------------
__device__ __forceinline__ uint32_t s2u(const void* p){
    uint32_t a;
    asm("{ .reg .u64 t; cvta.to.shared.u64 t, %1; cvt.u32.u64 %0, t; }" : "=r"(a) : "l"(p));
    return a;
}
__device__ __forceinline__ void ldsm4(uint32_t* r, uint32_t addr){
    asm volatile("ldmatrix.sync.aligned.m8n8.x4.shared.b16 {%0,%1,%2,%3}, [%4];"
        : "=r"(r[0]), "=r"(r[1]), "=r"(r[2]), "=r"(r[3]) : "r"(addr));
}
__device__ __forceinline__ void mma16816(float* c, const uint32_t* a, const uint32_t* b){
    asm volatile("mma.sync.aligned.m16n8k16.row.col.f32.bf16.bf16.f32 "
        "{%0,%1,%2,%3}, {%4,%5,%6,%7}, {%8,%9}, {%0,%1,%2,%3};"
        : "+f"(c[0]), "+f"(c[1]), "+f"(c[2]), "+f"(c[3])
        : "r"(a[0]), "r"(a[1]), "r"(a[2]), "r"(a[3]), "r"(b[0]), "r"(b[1]));
}
// hi bf16 pair = truncated top-16 bits of (x,y)
__device__ __forceinline__ uint2 hi_pair(float4 v){
    uint32_t x = __float_as_uint(v.x), y = __float_as_uint(v.y);
    uint32_t z = __float_as_uint(v.z), w = __float_as_uint(v.w);
    uint32_t h0, h1;
    asm("prmt.b32 %0, %1, %2, 0x7632;" : "=r"(h0) : "r"(x), "r"(y));
    asm("prmt.b32 %0, %1, %2, 0x7632;" : "=r"(h1) : "r"(z), "r"(w));
    return make_uint2(h0, h1);
}
// lo residual pair (exact subtract of truncated hi, then rn to bf16)
__device__ __forceinline__ uint2 lo_pair(float4 v){
    float lx = v.x - __uint_as_float(__float_as_uint(v.x) & 0xFFFF0000u);
    float ly = v.y - __uint_as_float(__float_as_uint(v.y) & 0xFFFF0000u);
    float lz = v.z - __uint_as_float(__float_as_uint(v.z) & 0xFFFF0000u);
    float lw = v.w - __uint_as_float(__float_as_uint(v.w) & 0xFFFF0000u);
    uint32_t l0, l1;
    asm("cvt.rn.bf16x2.f32 %0, %1, %2;" : "=r"(l0) : "f"(ly), "f"(lx));
    asm("cvt.rn.bf16x2.f32 %0, %1, %2;" : "=r"(l1) : "f"(lw), "f"(lz));
    return make_uint2(l0, l1);
}
__device__ __forceinline__ unsigned long long fma2(unsigned long long a,
        unsigned long long b, unsigned long long c){
    unsigned long long d;
    asm("fma.rn.f32x2 %0, %1, %2, %3;" : "=l"(d) : "l"(a), "l"(b), "l"(c));
    return d;
}
__device__ __forceinline__ unsigned long long packf2(float x, float y){
    unsigned long long r;
    asm("mov.b64 %0, {%1, %2};" : "=l"(r) : "f"(x), "f"(y));
    return r;
}
__device__ __forceinline__ float hsum2(unsigned long long v){
    return __uint_as_float((uint32_t)v) + __uint_as_float((uint32_t)(v >> 32));
}
__device__ __forceinline__ float sigf(float x){
    return __fdividef(1.0f, 1.0f + __expf(-x));
}
__device__ __forceinline__ float tanhfast(float x){
    return 2.0f * __fdividef(1.0f, 1.0f + __expf(-2.0f * x)) - 1.0f;
}

// ---------------------------------------------------------------------------
// Kernel 1: x1 GEMM via split-bf16 mma.sync (3 passes: hh + lh + hl).
// (unchanged from round 6 — 263us, protected)
// ---------------------------------------------------------------------------
#define PITCH 80
#define TILE_B (128 * PITCH)      // 10240
#define O_AHI 0
#define O_ALO (1 * TILE_B)
#define O_BHI (2 * TILE_B)
#define O_BLO (3 * TILE_B)
#define BUFB  (4 * TILE_B)        // 40960
#define GSMEM (2 * BUFB)          // 81920

__global__ __launch_bounds__(256, 1) void x1_gemm_hmma(
    const float* __restrict__ A,
    const float* __restrict__ W,
    const float* __restrict__ bih,
    const float* __restrict__ bhh)
{
    extern __shared__ __align__(128) char smg[];
    __shared__ float biasS[128];
    const int tid  = threadIdx.x;
    const int lane = tid & 31, wid = tid >> 5;
    const int wm = wid & 3, wn = wid >> 2;
    const int m0 = blockIdx.y << 7, n0 = blockIdx.x << 7;

    if (tid < 128) biasS[tid] = bih[n0 + tid] + bhh[n0 + tid];

    const int lrow = tid >> 3;
    const int lc4  = tid & 7;
    const float* Abase = A + (size_t)(m0 + lrow) * DIN + lc4 * 4;
    const float* Wbase = W + (size_t)(n0 + lrow) * DIN + lc4 * 4;
    const int soff = lrow * PITCH + lc4 * 8;

    const uint32_t sbase = s2u(smg);
    const uint32_t a_off = (uint32_t)((wm * 32 + (lane & 15)) * PITCH + (lane >> 4) * 16);
    const uint32_t b_off = (uint32_t)((wn * 64 + (lane & 7) + 8 * (lane >> 4)) * PITCH
                                      + ((lane >> 3) & 1) * 16);

    float c[2][8][4];
    #pragma unroll
    for (int i = 0; i < 2; i++)
        #pragma unroll
        for (int j = 0; j < 8; j++)
            #pragma unroll
            for (int k = 0; k < 4; k++) c[i][j][k] = 0.f;

    float4 ra[4], rw[4];
    #pragma unroll
    for (int i = 0; i < 4; i++){
        ra[i] = *(const float4*)(Abase + (size_t)(32 * i) * DIN);
        rw[i] = *(const float4*)(Wbase + (size_t)(32 * i) * DIN);
    }
    #pragma unroll
    for (int i = 0; i < 4; i++){
        int off = soff + i * 32 * PITCH;
        *(uint2*)(smg + O_AHI + off) = hi_pair(ra[i]);
        *(uint2*)(smg + O_ALO + off) = lo_pair(ra[i]);
        *(uint2*)(smg + O_BHI + off) = hi_pair(rw[i]);
        *(uint2*)(smg + O_BLO + off) = lo_pair(rw[i]);
    }
    __syncthreads();

    for (int ci = 0; ci < 32; ci++){
        const uint32_t buf = sbase + (uint32_t)(ci & 1) * BUFB;
        if (ci < 31){
            #pragma unroll
            for (int i = 0; i < 4; i++){
                ra[i] = *(const float4*)(Abase + (size_t)(32 * i) * DIN + (ci + 1) * 32);
                rw[i] = *(const float4*)(Wbase + (size_t)(32 * i) * DIN + (ci + 1) * 32);
            }
        }
        #pragma unroll
        for (int kk = 0; kk < 2; kk++){
            uint32_t ah0[4], ah1[4], al0[4], al1[4], bh[4][4], bl[4][4];
            const uint32_t ka = a_off + kk * 32;
            const uint32_t kb = b_off + kk * 32;
            ldsm4(ah0, buf + O_AHI + ka);
            ldsm4(ah1, buf + O_AHI + ka + 16 * PITCH);
            ldsm4(al0, buf + O_ALO + ka);
            ldsm4(al1, buf + O_ALO + ka + 16 * PITCH);
            #pragma unroll
            for (int q2 = 0; q2 < 4; q2++){
                ldsm4(bh[q2], buf + O_BHI + kb + q2 * 16 * PITCH);
                ldsm4(bl[q2], buf + O_BLO + kb + q2 * 16 * PITCH);
            }
            #pragma unroll
            for (int nt = 0; nt < 8; nt++){
                const uint32_t* bhp = &bh[nt >> 1][(nt & 1) * 2];
                const uint32_t* blp = &bl[nt >> 1][(nt & 1) * 2];
                mma16816(c[0][nt], ah0, bhp);
                mma16816(c[1][nt], ah1, bhp);
                mma16816(c[0][nt], al0, bhp);
                mma16816(c[1][nt], al1, bhp);
                mma16816(c[0][nt], ah0, blp);
                mma16816(c[1][nt], ah1, blp);
            }
        }
        if (ci < 31){
            char* b = smg + ((ci + 1) & 1) * BUFB;
            #pragma unroll
            for (int i = 0; i < 4; i++){
                int off = soff + i * 32 * PITCH;
                *(uint2*)(b + O_AHI + off) = hi_pair(ra[i]);
                *(uint2*)(b + O_ALO + off) = lo_pair(ra[i]);
                *(uint2*)(b + O_BHI + off) = hi_pair(rw[i]);
                *(uint2*)(b + O_BLO + off) = lo_pair(rw[i]);
            }
        }
        __syncthreads();
    }

    const int gr = lane >> 2;
    const int gc = (lane & 3) * 2;
    #pragma unroll
    for (int mt = 0; mt < 2; mt++){
        #pragma unroll
        for (int nt = 0; nt < 8; nt++){
            const int n = wn * 64 + nt * 8 + gc;
            const float b0 = biasS[n], b1 = biasS[n + 1];
            #pragma unroll
            for (int rr = 0; rr < 2; rr++){
                const int m = m0 + wm * 32 + mt * 16 + gr + rr * 8;
                const int bb = m >> 9;
                const int tt = m & 511;
                float2 o = make_float2(c[mt][nt][rr * 2 + 0] + b0,
                                       c[mt][nt][rr * 2 + 1] + b1);
                *(float2*)(g_x1 + ((size_t)tt * BATCH + bb) * GATES + n0 + n) = o;
            }
        }
    }
}

// ---------------------------------------------------------------------------
// Kernel 2: recurrence. 32 clusters x 4 CTAs, 2 batches/cluster.
// In-warp half-split: lane = half*16 + g*4 + jo; warp w owns j in [4w,4w+4).
// Cross-half reduction via shfl_xor(16), gate redistribution via 16 shfl.idx
// -> no mid-step __syncthreads, cell state in registers, gates on all 8 warps.
// Cluster sync: DSMEM mbarrier (32 arrivals: 8 warps x 4 CTAs), acquire wait.
// ---------------------------------------------------------------------------
__device__ __forceinline__ void bcast4(const float* addr, float v){
    uint32_t la = (uint32_t)__cvta_generic_to_shared(addr);
    #pragma unroll
    for (int pr = 0; pr < 4; pr++){
        uint32_t raddr;
        asm volatile("mapa.shared::cluster.u32 %0, %1, %2;" : "=r"(raddr) : "r"(la), "r"(pr));
        asm volatile("st.shared::cluster.f32 [%0], %1;" :: "r"(raddr), "f"(v) : "memory");
    }
}
__device__ __forceinline__ void arrive4(uint32_t la){
    #pragma unroll
    for (int pr = 0; pr < 4; pr++){
        uint32_t raddr;
        asm volatile("mapa.shared::cluster.u32 %0, %1, %2;" : "=r"(raddr) : "r"(la), "r"(pr));
        asm volatile("mbarrier.arrive.shared::cluster.b64 _, [%0];" :: "r"(raddr) : "memory");
    }
}
__device__ __forceinline__ void mbar_wait_c(uint32_t mb, uint32_t parity){
    asm volatile(
        "{\n\t.reg .pred P;\n\t"
        "WL_%=:\n\t"
        "mbarrier.try_wait.parity.acquire.cluster.shared::cta.b64 P, [%0], %1;\n\t"
        "@!P bra WL_%=;\n\t"
        "}\n" :: "r"(mb), "r"(parity) : "memory");
}

__global__ void __cluster_dims__(4,1,1) __launch_bounds__(256, 1)
lstm_rec_kernel(const float* __restrict__ Whh1,
                const float* __restrict__ Wih2,
                const float* __restrict__ Whh2,
                const float* __restrict__ bih2,
                const float* __restrict__ bhh2,
                float* __restrict__ out)
{
    __shared__ __align__(16) float h1s[2][2][HID];
    __shared__ __align__(16) float h2s[2][2][HID];
    __shared__ __align__(8) unsigned long long mbar;

    const int tid  = threadIdx.x;
    const int w    = tid >> 5;
    const int lane = tid & 31;
    const int half = lane >> 4;         // k-half
    const int u    = lane & 15;
    const int g    = u >> 2;            // gate 0..3
    const int jo   = u & 3;
    const int jj   = w * 4 + jo;        // j within this CTA's 32-slice
    uint32_t rank;
    asm("mov.u32 %0, %%cluster_ctarank;" : "=r"(rank));
    const int b0   = (blockIdx.x >> 2) * 2;
    const int grow = g * 128 + (int)rank * 32 + jj;
    const uint32_t mba = (uint32_t)__cvta_generic_to_shared(&mbar);

    // register-resident packed weight slices
    unsigned long long w1p[32], w2p[32], w3p[32];
    {
        const float4* p1 = (const float4*)(Whh1 + (size_t)grow * HID + half * 64);
        const float4* p2 = (const float4*)(Wih2 + (size_t)grow * HID + half * 64);
        const float4* p3 = (const float4*)(Whh2 + (size_t)grow * HID + half * 64);
        #pragma unroll
        for (int k = 0; k < 16; k++){
            float4 v1 = p1[k], v2 = p2[k], v3 = p3[k];
            w1p[2*k]   = packf2(v1.x, v1.y);  w1p[2*k+1] = packf2(v1.z, v1.w);
            w2p[2*k]   = packf2(v2.x, v2.y);  w2p[2*k+1] = packf2(v2.z, v2.w);
            w3p[2*k]   = packf2(v3.x, v3.y);  w3p[2*k+1] = packf2(v3.z, v3.w);
        }
    }
    const float b2v = bih2[grow] + bhh2[grow];

    for (int i = tid; i < 2*2*HID; i += 256){
        (&h1s[0][0][0])[i] = 0.f;
        (&h2s[0][0][0])[i] = 0.f;
    }
    if (tid == 0){
        asm volatile("mbarrier.init.shared.b64 [%0], %1;" :: "r"(mba), "r"(32u) : "memory");
    }
    __syncthreads();
    asm volatile("barrier.cluster.arrive.aligned;" ::: "memory");
    asm volatile("barrier.cluster.wait.aligned;"   ::: "memory");

    // Prologue: layer1(t=0) from x only. Gate-unit lanes 0-7 own c1, 8-15 own c2.
    float cst = 0.f;
    if (lane < 8){
        const int b = (lane >> 2) & 1;
        const float* xp = g_x1 + ((size_t)0 * BATCH + b0 + b) * GATES + (int)rank * 32 + jj;
        float p0 = xp[0], p2 = xp[256], p3 = xp[384];
        cst = sigf(p0) * tanhfast(p2);
        float h = sigf(p3) * tanhfast(cst);
        bcast4(&h1s[0][b][(int)rank * 32 + jj], h);
    }
    __syncwarp();
    if (lane == 0) arrive4(mba);
    float xv0 = 0.f, xv1 = 0.f;
    if (half == 0){
        const float* xp = g_x1 + ((size_t)1 * BATCH + b0) * GATES + grow;
        xv0 = xp[0];
        xv1 = xp[GATES];
    }
    mbar_wait_c(mba, 0);

    int cur = 0;
    for (int t = 0; t < T_STEPS; t++){
        const int nxt = cur ^ 1;

        // packed dot products for layer1(t+1) and layer2(t)
        const float4* A0 = (const float4*)&h1s[cur][0][half * 64];
        const float4* A1 = (const float4*)&h1s[cur][1][half * 64];
        const float4* D0 = (const float4*)&h2s[cur][0][half * 64];
        const float4* D1 = (const float4*)&h2s[cur][1][half * 64];
        unsigned long long q10 = 0ull, q11 = 0ull;
        unsigned long long q20 = 0ull, q21 = 0ull, r20 = 0ull, r21 = 0ull;
        #pragma unroll
        for (int k4 = 0; k4 < 16; k4++){
            float4 a0 = A0[k4], a1 = A1[k4], d0 = D0[k4], d1 = D1[k4];
            unsigned long long a0p = packf2(a0.x, a0.y), a0q = packf2(a0.z, a0.w);
            unsigned long long a1p = packf2(a1.x, a1.y), a1q = packf2(a1.z, a1.w);
            unsigned long long d0p = packf2(d0.x, d0.y), d0q = packf2(d0.z, d0.w);
            unsigned long long d1p = packf2(d1.x, d1.y), d1q = packf2(d1.z, d1.w);
            q10 = fma2(w1p[2*k4], a0p, q10);  q10 = fma2(w1p[2*k4+1], a0q, q10);
            q11 = fma2(w1p[2*k4], a1p, q11);  q11 = fma2(w1p[2*k4+1], a1q, q11);
            q20 = fma2(w2p[2*k4], a0p, q20);  q20 = fma2(w2p[2*k4+1], a0q, q20);
            q21 = fma2(w2p[2*k4], a1p, q21);  q21 = fma2(w2p[2*k4+1], a1q, q21);
            r20 = fma2(w3p[2*k4], d0p, r20);  r20 = fma2(w3p[2*k4+1], d0q, r20);
            r21 = fma2(w3p[2*k4], d1p, r21);  r21 = fma2(w3p[2*k4+1], d1q, r21);
        }
        float s10 = hsum2(q10) + xv0;
        float s11 = hsum2(q11) + xv1;
        float s20 = hsum2(q20) + hsum2(r20) + (half ? 0.f : b2v);
        float s21 = hsum2(q21) + hsum2(r21) + (half ? 0.f : b2v);
        s10 += __shfl_xor_sync(0xFFFFFFFFu, s10, 16);
        s11 += __shfl_xor_sync(0xFFFFFFFFu, s11, 16);
        s20 += __shfl_xor_sync(0xFFFFFFFFu, s20, 16);
        s21 += __shfl_xor_sync(0xFFFFFFFFu, s21, 16);

        // redistribute: target lane<16 gathers all 4 gates of its unit
        float t10[4], t11[4], t20[4], t21[4];
        #pragma unroll
        for (int gg = 0; gg < 4; gg++){
            int src = gg * 4 + (lane & 3);
            t10[gg] = __shfl_sync(0xFFFFFFFFu, s10, src);
            t11[gg] = __shfl_sync(0xFFFFFFFFu, s11, src);
            t20[gg] = __shfl_sync(0xFFFFFFFFu, s20, src);
            t21[gg] = __shfl_sync(0xFFFFFFFFu, s21, src);
        }

        float outv = 0.f;
        if (lane < 16){
            const int L = lane >> 3;             // 0: layer1(t+1), 1: layer2(t)
            const int b = (lane >> 2) & 1;
            float p0, p1, p2, p3;
            if (L == 0){
                p0 = b ? t11[0] : t10[0];  p1 = b ? t11[1] : t10[1];
                p2 = b ? t11[2] : t10[2];  p3 = b ? t11[3] : t10[3];
            } else {
                p0 = b ? t21[0] : t20[0];  p1 = b ? t21[1] : t20[1];
                p2 = b ? t21[2] : t20[2];  p3 = b ? t21[3] : t20[3];
            }
            if (L == 1 || t < T_STEPS - 1){
                float cn = sigf(p1) * cst + sigf(p0) * tanhfast(p2);
                cst = cn;
                float h = sigf(p3) * tanhfast(cn);
                if (L == 0){
                    bcast4(&h1s[nxt][b][(int)rank * 32 + jj], h);
                } else {
                    bcast4(&h2s[nxt][b][(int)rank * 32 + jj], h);
                    outv = h;
                }
            }
        }
        __syncwarp();
        if (lane == 0) arrive4(mba);

        // hidden in the arrive->wait window: output store + x prefetch (t+2)
        if (lane >= 8 && lane < 16)
            out[((size_t)(b0 + ((lane >> 2) & 1)) * T_STEPS + t) * HID + (int)rank * 32 + jj] = outv;
        float nx0 = 0.f, nx1 = 0.f;
        if (half == 0 && t < T_STEPS - 2){
            const float* xp = g_x1 + ((size_t)(t + 2) * BATCH + b0) * GATES + grow;
            nx0 = xp[0];
            nx1 = xp[GATES];
        }

        mbar_wait_c(mba, (t + 1) & 1);
        xv0 = nx0; xv1 = nx1;
        cur = nxt;
    }
}

// ---------------------------------------------------------------------------
extern "C" void kernel_launch(void* const* d_in, const int* in_sizes, int n_in,
                              void* d_out, int out_size)
{
    (void)in_sizes; (void)n_in; (void)out_size;
    const float* feats = (const float*)d_in[0];
    const float* W_ih1 = (const float*)d_in[1];
    const float* W_hh1 = (const float*)d_in[2];
    const float* b_ih1 = (const float*)d_in[3];
    const float* b_hh1 = (const float*)d_in[4];
    const float* W_ih2 = (const float*)d_in[5];
    const float* W_hh2 = (const float*)d_in[6];
    const float* b_ih2 = (const float*)d_in[7];
    const float* b_hh2 = (const float*)d_in[8];
    float* out = (float*)d_out;

    cudaFuncSetAttribute(x1_gemm_hmma, cudaFuncAttributeMaxDynamicSharedMemorySize, GSMEM);

    dim3 g1(GATES / 128, (BATCH * T_STEPS) / 128);   // (4, 256)
    x1_gemm_hmma<<<g1, 256, GSMEM>>>(feats, W_ih1, b_ih1, b_hh1);

    lstm_rec_kernel<<<128, 256>>>(W_hh1, W_ih2, W_hh2, b_ih2, b_hh2, out);
}